// round 16
// baseline (speedup 1.0000x reference)
#include <cuda_runtime.h>
#include <cuda_fp16.h>
#include <cstdint>

#define N_NODES 100000
#define N_EDGES 1600000
#define D 128
#define TILE_R 128
#define SA_K 264                     // padded k-stride (halves)
#define MMA_THREADS 512
#define A_BUF_H (TILE_R * SA_K)      // halves per A buffer
// smem: A0 + A1 + B[128][264]h + bias[128]f + snorm[128][2]f
#define SMEM_MMA (2*A_BUF_H*2 + 128*SA_K*2 + 128*4 + 256*4)   // 204288

// ---------------- device scratch ----------------
__device__ __align__(16) __half g_agg16[(size_t)N_NODES * D];
__device__ __align__(16) __half g_f16[(size_t)N_NODES * D];
__device__ __align__(16) int    g_degi[N_NODES];
__device__ __align__(16) int    g_rowstart[N_NODES];
__device__ __align__(16) int    g_cursor[N_NODES];
__device__ __align__(16) int    g_col[N_EDGES];

// ---------------- helpers ----------------
__device__ __forceinline__ uint32_t smem_u32(const void* p) {
    uint32_t a;
    asm("{ .reg .u64 t; cvta.to.shared.u64 t, %1; cvt.u32.u64 %0, t; }" : "=r"(a) : "l"(p));
    return a;
}
__device__ __forceinline__ void ldsm_x4(uint32_t& r0, uint32_t& r1, uint32_t& r2,
                                        uint32_t& r3, uint32_t addr) {
    asm volatile("ldmatrix.sync.aligned.m8n8.x4.shared.b16 {%0,%1,%2,%3}, [%4];"
                 : "=r"(r0), "=r"(r1), "=r"(r2), "=r"(r3) : "r"(addr));
}
__device__ __forceinline__ void mma16816(float* d, const uint32_t* a,
                                         uint32_t b0, uint32_t b1) {
    asm volatile(
        "mma.sync.aligned.m16n8k16.row.col.f32.f16.f16.f32 "
        "{%0,%1,%2,%3}, {%4,%5,%6,%7}, {%8,%9}, {%0,%1,%2,%3};"
        : "+f"(d[0]), "+f"(d[1]), "+f"(d[2]), "+f"(d[3])
        : "r"(a[0]), "r"(a[1]), "r"(a[2]), "r"(a[3]), "r"(b0), "r"(b1));
}
__device__ __forceinline__ uint32_t h2u(__half2 h) { return *(uint32_t*)&h; }
__device__ __forceinline__ void cp_async16(uint32_t dst, const void* src, int src_sz) {
    asm volatile("cp.async.cg.shared.global [%0], [%1], 16, %2;"
                 :: "r"(dst), "l"(src), "r"(src_sz) : "memory");
}
__device__ __forceinline__ void cp_commit() {
    asm volatile("cp.async.commit_group;" ::: "memory");
}
__device__ __forceinline__ void cp_wait0() {
    asm volatile("cp.async.wait_group 0;" ::: "memory");
}

// ---------------- fused degree histogram + x -> fp16 ----------------
__global__ void degx2h_kernel(const int* __restrict__ dst, int* __restrict__ degi,
                              const float* __restrict__ x, __half* __restrict__ x16) {
    int i = blockIdx.x * blockDim.x + threadIdx.x;
    if (i < N_EDGES) atomicAdd(&degi[dst[i]], 1);
    if (i < N_NODES * D / 4) {
        float4 v = *(const float4*)(x + (size_t)i * 4);
        __half2 a = __floats2half2_rn(v.x, v.y);
        __half2 b = __floats2half2_rn(v.z, v.w);
        *(uint2*)(x16 + (size_t)i * 4) = make_uint2(h2u(a), h2u(b));
    }
}

// ---------------- single-block pass-based exclusive scan ----------------
__global__ void scan_kernel(const int* __restrict__ deg,
                            int* __restrict__ rowstart, int* __restrict__ cursor) {
    __shared__ int wsums[32];
    __shared__ int running_s;
    const int t = threadIdx.x;
    const int lane = t & 31, w = t >> 5;
    if (t == 0) running_s = 0;
    __syncthreads();

    for (int base = 0; base < N_NODES; base += 4096) {
        int i0 = base + t * 4;
        int4 d4 = make_int4(0, 0, 0, 0);
        if (i0 + 3 < N_NODES) d4 = *(const int4*)(deg + i0);
        else {
            if (i0 + 0 < N_NODES) d4.x = deg[i0 + 0];
            if (i0 + 1 < N_NODES) d4.y = deg[i0 + 1];
            if (i0 + 2 < N_NODES) d4.z = deg[i0 + 2];
        }
        int tsum = d4.x + d4.y + d4.z + d4.w;
        int sc = tsum;
#pragma unroll
        for (int m = 1; m < 32; m <<= 1) {
            int u = __shfl_up_sync(0xffffffffu, sc, m);
            if (lane >= m) sc += u;
        }
        if (lane == 31) wsums[w] = sc;
        __syncthreads();
        if (w == 0) {
            int s2 = wsums[lane];
#pragma unroll
            for (int m = 1; m < 32; m <<= 1) {
                int u = __shfl_up_sync(0xffffffffu, s2, m);
                if (lane >= m) s2 += u;
            }
            wsums[lane] = s2;
        }
        __syncthreads();
        int excl = running_s + (w > 0 ? wsums[w - 1] : 0) + sc - tsum;
        int r = excl;
        if (i0 + 0 < N_NODES) { rowstart[i0 + 0] = r; cursor[i0 + 0] = r; } r += d4.x;
        if (i0 + 1 < N_NODES) { rowstart[i0 + 1] = r; cursor[i0 + 1] = r; } r += d4.y;
        if (i0 + 2 < N_NODES) { rowstart[i0 + 2] = r; cursor[i0 + 2] = r; } r += d4.z;
        if (i0 + 3 < N_NODES) { rowstart[i0 + 3] = r; cursor[i0 + 3] = r; }
        int total = wsums[31];
        __syncthreads();
        if (t == 0) running_s += total;
        __syncthreads();
    }
}

__global__ void fill_kernel(const int* __restrict__ src, const int* __restrict__ dst,
                            int* __restrict__ cursor, int* __restrict__ col) {
    int e = blockIdx.x * blockDim.x + threadIdx.x;
    if (e < N_EDGES) {
        int d = dst[e];
        int p = atomicAdd(&cursor[d], 1);
        col[p] = src[e];
    }
}

// ---------------- gather-mean: node per half-warp, int4 col loads, MLP 8 -----
__global__ void gather16_kernel(const __half* __restrict__ feat16,
                                const int* __restrict__ row_start,
                                const int* __restrict__ degi,
                                const int* __restrict__ col,
                                __half* __restrict__ agg16) {
    int node = (blockIdx.x * blockDim.x + threadIdx.x) >> 4;
    if (node >= N_NODES) return;
    const int l16 = threadIdx.x & 15;
    const int c8 = l16 << 3;            // 8 halves = 16B per lane
    const int start = row_start[node];
    const int len = degi[node];
    const int end = start + len;

    float a0[8], a1[8];
#pragma unroll
    for (int i = 0; i < 8; i++) { a0[i] = 0.f; a1[i] = 0.f; }

    int e = start;
    // peel to 4-alignment for int4 col loads
    while (e < end && (e & 3)) {
        int s = __ldg(&col[e]);
        uint4 v = *(const uint4*)(feat16 + (size_t)s * D + c8);
        float2 f0 = __half22float2(*(__half2*)&v.x);
        float2 f1 = __half22float2(*(__half2*)&v.y);
        float2 f2 = __half22float2(*(__half2*)&v.z);
        float2 f3 = __half22float2(*(__half2*)&v.w);
        a0[0] += f0.x; a0[1] += f0.y; a0[2] += f1.x; a0[3] += f1.y;
        a0[4] += f2.x; a0[5] += f2.y; a0[6] += f3.x; a0[7] += f3.y;
        e++;
    }
    // main: 8 edges per iter, 2 int4 col loads, dual acc chains
    for (; e + 8 <= end; e += 8) {
        int4 ca = __ldg((const int4*)(col + e));
        int4 cb = __ldg((const int4*)(col + e + 4));
        uint4 v[8];
        v[0] = *(const uint4*)(feat16 + (size_t)ca.x * D + c8);
        v[1] = *(const uint4*)(feat16 + (size_t)ca.y * D + c8);
        v[2] = *(const uint4*)(feat16 + (size_t)ca.z * D + c8);
        v[3] = *(const uint4*)(feat16 + (size_t)ca.w * D + c8);
        v[4] = *(const uint4*)(feat16 + (size_t)cb.x * D + c8);
        v[5] = *(const uint4*)(feat16 + (size_t)cb.y * D + c8);
        v[6] = *(const uint4*)(feat16 + (size_t)cb.z * D + c8);
        v[7] = *(const uint4*)(feat16 + (size_t)cb.w * D + c8);
#pragma unroll
        for (int p = 0; p < 4; p++) {
            float* acc = (p & 1) ? a1 : a0;
            __half2 q0 = __hadd2(*(__half2*)&v[2*p].x, *(__half2*)&v[2*p+1].x);
            __half2 q1 = __hadd2(*(__half2*)&v[2*p].y, *(__half2*)&v[2*p+1].y);
            __half2 q2 = __hadd2(*(__half2*)&v[2*p].z, *(__half2*)&v[2*p+1].z);
            __half2 q3 = __hadd2(*(__half2*)&v[2*p].w, *(__half2*)&v[2*p+1].w);
            float2 f0 = __half22float2(q0), f1 = __half22float2(q1);
            float2 f2 = __half22float2(q2), f3 = __half22float2(q3);
            acc[0] += f0.x; acc[1] += f0.y; acc[2] += f1.x; acc[3] += f1.y;
            acc[4] += f2.x; acc[5] += f2.y; acc[6] += f3.x; acc[7] += f3.y;
        }
    }
    // 4-edge batch
    if (e + 4 <= end) {
        int4 ca = __ldg((const int4*)(col + e));
        uint4 v[4];
        v[0] = *(const uint4*)(feat16 + (size_t)ca.x * D + c8);
        v[1] = *(const uint4*)(feat16 + (size_t)ca.y * D + c8);
        v[2] = *(const uint4*)(feat16 + (size_t)ca.z * D + c8);
        v[3] = *(const uint4*)(feat16 + (size_t)ca.w * D + c8);
#pragma unroll
        for (int p = 0; p < 2; p++) {
            float* acc = (p & 1) ? a1 : a0;
            __half2 q0 = __hadd2(*(__half2*)&v[2*p].x, *(__half2*)&v[2*p+1].x);
            __half2 q1 = __hadd2(*(__half2*)&v[2*p].y, *(__half2*)&v[2*p+1].y);
            __half2 q2 = __hadd2(*(__half2*)&v[2*p].z, *(__half2*)&v[2*p+1].z);
            __half2 q3 = __hadd2(*(__half2*)&v[2*p].w, *(__half2*)&v[2*p+1].w);
            float2 f0 = __half22float2(q0), f1 = __half22float2(q1);
            float2 f2 = __half22float2(q2), f3 = __half22float2(q3);
            acc[0] += f0.x; acc[1] += f0.y; acc[2] += f1.x; acc[3] += f1.y;
            acc[4] += f2.x; acc[5] += f2.y; acc[6] += f3.x; acc[7] += f3.y;
        }
        e += 4;
    }
    // scalar tail (0-3 edges)
    for (; e < end; e++) {
        int s = __ldg(&col[e]);
        uint4 v = *(const uint4*)(feat16 + (size_t)s * D + c8);
        float2 f0 = __half22float2(*(__half2*)&v.x);
        float2 f1 = __half22float2(*(__half2*)&v.y);
        float2 f2 = __half22float2(*(__half2*)&v.z);
        float2 f3 = __half22float2(*(__half2*)&v.w);
        a0[0] += f0.x; a0[1] += f0.y; a0[2] += f1.x; a0[3] += f1.y;
        a0[4] += f2.x; a0[5] += f2.y; a0[6] += f3.x; a0[7] += f3.y;
    }
    const float inv = 1.0f / fmaxf((float)len, 1.0f);
    uint4 o;
    o.x = h2u(__floats2half2_rn((a0[0] + a1[0]) * inv, (a0[1] + a1[1]) * inv));
    o.y = h2u(__floats2half2_rn((a0[2] + a1[2]) * inv, (a0[3] + a1[3]) * inv));
    o.z = h2u(__floats2half2_rn((a0[4] + a1[4]) * inv, (a0[5] + a1[5]) * inv));
    o.w = h2u(__floats2half2_rn((a0[6] + a1[6]) * inv, (a0[7] + a1[7]) * inv));
    __stcs((uint4*)(agg16 + (size_t)node * D + c8), o);
}

// ---------------- tensor-core SAGE layer, cp.async double-buffered -----------
__global__ void __launch_bounds__(MMA_THREADS, 1)
sage_mma_kernel(const __half* __restrict__ f16feat,
                const __half* __restrict__ agg16,
                const float* __restrict__ Ws,
                const float* __restrict__ Wn,
                const float* __restrict__ bias,
                float* __restrict__ out,       // may be null (layer 1)
                __half* __restrict__ out16,    // may be null (layer 2)
                int do_norm) {
    extern __shared__ __half sh[];
    __half* sA = sh;                               // 2 x [128][SA_K]
    __half* sB = sh + 2 * A_BUF_H;                 // [128][SA_K]
    float* sbias = (float*)(sB + 128 * SA_K);      // [128]
    float* snorm = sbias + 128;                    // [128][2]

    const int tid = threadIdx.x;
    const int wid = tid >> 5;
    const int lane = tid & 31;
    const int warp_m = wid & 7;
    const int warp_n = wid >> 3;

    const uint32_t sA_addr = smem_u32(sA);
    const uint32_t sB_addr = smem_u32(sB);

    // ---- A tile staging via cp.async: 4096 16B chunks, 8 per thread ----
    auto stageA = [&](int tile, int buf) {
        const int row0 = tile * TILE_R;
        const uint32_t bbase = sA_addr + (uint32_t)buf * (A_BUF_H * 2);
#pragma unroll
        for (int i = 0; i < 8; i++) {
            int c = tid + i * MMA_THREADS;       // 0..4095
            int r = c >> 5;
            int cc = c & 31;                     // 16B chunk within row
            int grow = row0 + r;
            int valid = (grow < N_NODES) ? 16 : 0;
            int g = (grow < N_NODES) ? grow : 0;
            const __half* src = (cc < 16)
                ? f16feat + (size_t)g * D + cc * 8
                : agg16 + (size_t)g * D + (cc - 16) * 8;
            cp_async16(bbase + (uint32_t)(r * SA_K * 2 + cc * 16), src, valid);
        }
        cp_commit();
    };

    // ---- stage B (weights) once: row j, quarter q (64 halves) ----
    {
        int j = tid >> 2, q = tid & 3;
        const float* W = (q < 2) ? Ws : Wn;
        const float4* wr = (const float4*)(W + j * D + (q & 1) * 64);
        uint4* drow = (uint4*)(sB + j * SA_K + q * 64);
#pragma unroll
        for (int q2 = 0; q2 < 8; q2++) {
            float4 v0 = wr[q2 * 2], v1 = wr[q2 * 2 + 1];
            drow[q2] = make_uint4(h2u(__floats2half2_rn(v0.x, v0.y)),
                                  h2u(__floats2half2_rn(v0.z, v0.w)),
                                  h2u(__floats2half2_rn(v1.x, v1.y)),
                                  h2u(__floats2half2_rn(v1.z, v1.w)));
        }
    }
    if (tid < 128) sbias[tid] = bias[tid];

    const uint32_t a_off = ((warp_m * 16 + (lane & 15)) * SA_K + (lane >> 4) * 8) * 2;
    const uint32_t b_row = warp_n * 64 + (lane & 15);
    const uint32_t b_base = sB_addr + (b_row * SA_K + (lane >> 4) * 8) * 2;

    const int NT = (N_NODES + TILE_R - 1) / TILE_R;   // 782

    // prologue: prefetch first tile
    if (blockIdx.x < NT) stageA(blockIdx.x, 0);

    int buf = 0;
    for (int tile = blockIdx.x; tile < NT; tile += gridDim.x) {
        const int row0 = tile * TILE_R;

        cp_wait0();
        __syncthreads();

        // prefetch next tile into the other buffer (overlaps with mma below)
        int ntile = tile + gridDim.x;
        if (ntile < NT) stageA(ntile, buf ^ 1);

        // ---- mma mainloop: K = 256 in 16 k16 steps (full unroll) ----
        const uint32_t a_base = sA_addr + (uint32_t)buf * (A_BUF_H * 2) + a_off;
        float acc[8][4];
#pragma unroll
        for (int i = 0; i < 8; i++)
#pragma unroll
            for (int j = 0; j < 4; j++) acc[i][j] = 0.f;

#pragma unroll
        for (int ks = 0; ks < 16; ks++) {
            uint32_t a[4];
            ldsm_x4(a[0], a[1], a[2], a[3], a_base + ks * 32);
#pragma unroll
            for (int nf2 = 0; nf2 < 4; nf2++) {
                uint32_t b0, b1, b2, b3;
                ldsm_x4(b0, b1, b2, b3, b_base + nf2 * 16 * SA_K * 2 + ks * 32);
                mma16816(acc[nf2 * 2 + 0], a, b0, b2);
                mma16816(acc[nf2 * 2 + 1], a, b1, b3);
            }
        }

        // ---- epilogue: bias + (optional) cross-warp L2 norm ----
        const int tg = lane & 3;
        const int rr = lane >> 2;
        const int row_a = warp_m * 16 + rr;
        const int row_b = row_a + 8;

        float ss_a = 0.f, ss_b = 0.f;
#pragma unroll
        for (int nf = 0; nf < 8; nf++) {
            int n0 = warp_n * 64 + nf * 8 + tg * 2;
            acc[nf][0] += sbias[n0]; acc[nf][1] += sbias[n0 + 1];
            acc[nf][2] += sbias[n0]; acc[nf][3] += sbias[n0 + 1];
            ss_a += acc[nf][0] * acc[nf][0] + acc[nf][1] * acc[nf][1];
            ss_b += acc[nf][2] * acc[nf][2] + acc[nf][3] * acc[nf][3];
        }
        ss_a += __shfl_xor_sync(0xffffffffu, ss_a, 1);
        ss_a += __shfl_xor_sync(0xffffffffu, ss_a, 2);
        ss_b += __shfl_xor_sync(0xffffffffu, ss_b, 1);
        ss_b += __shfl_xor_sync(0xffffffffu, ss_b, 2);

        float scale_a = 1.f, scale_b = 1.f;
        if (do_norm) {
            if (tg == 0) {
                snorm[row_a * 2 + warp_n] = ss_a;
                snorm[row_b * 2 + warp_n] = ss_b;
            }
            __syncthreads();
            float fa = snorm[row_a * 2 + 0] + snorm[row_a * 2 + 1];
            float fb = snorm[row_b * 2 + 0] + snorm[row_b * 2 + 1];
            scale_a = 1.0f / fmaxf(sqrtf(fa), 1e-12f);
            scale_b = 1.0f / fmaxf(sqrtf(fb), 1e-12f);
        }

        int grow_a = row0 + row_a;
        int grow_b = row0 + row_b;
#pragma unroll
        for (int nf = 0; nf < 8; nf++) {
            int n0 = warp_n * 64 + nf * 8 + tg * 2;
            if (grow_a < N_NODES) {
                float v0 = acc[nf][0] * scale_a, v1 = acc[nf][1] * scale_a;
                if (out) *(float2*)(out + (size_t)grow_a * D + n0) = make_float2(v0, v1);
                if (out16) *(__half2*)(out16 + (size_t)grow_a * D + n0) = __floats2half2_rn(v0, v1);
            }
            if (grow_b < N_NODES) {
                float v0 = acc[nf][2] * scale_b, v1 = acc[nf][3] * scale_b;
                if (out) *(float2*)(out + (size_t)grow_b * D + n0) = make_float2(v0, v1);
                if (out16) *(__half2*)(out16 + (size_t)grow_b * D + n0) = __floats2half2_rn(v0, v1);
            }
        }
        buf ^= 1;
        __syncthreads();   // all reads of buf done before it is refilled next iter
    }
}

// ---------------- launch ----------------
extern "C" void kernel_launch(void* const* d_in, const int* in_sizes, int n_in,
                              void* d_out, int out_size) {
    const float* x   = (const float*)d_in[0];
    const int* src   = (const int*)d_in[1];
    const int* dst   = (const int*)d_in[2];
    const float* Ws1 = (const float*)d_in[3];
    const float* Wn1 = (const float*)d_in[4];
    const float* b1  = (const float*)d_in[5];
    const float* Ws2 = (const float*)d_in[6];
    const float* Wn2 = (const float*)d_in[7];
    const float* b2  = (const float*)d_in[8];
    float* out = (float*)d_out;

    __half* agg16; cudaGetSymbolAddress((void**)&agg16, g_agg16);
    __half* f16;   cudaGetSymbolAddress((void**)&f16, g_f16);
    int* degi;     cudaGetSymbolAddress((void**)&degi, g_degi);
    int* rowst;    cudaGetSymbolAddress((void**)&rowst, g_rowstart);
    int* cursor;   cudaGetSymbolAddress((void**)&cursor, g_cursor);
    int* col;      cudaGetSymbolAddress((void**)&col, g_col);

    int sms = 148;
    cudaDeviceGetAttribute(&sms, cudaDevAttrMultiProcessorCount, 0);
    cudaFuncSetAttribute(sage_mma_kernel,
                         cudaFuncAttributeMaxDynamicSharedMemorySize, SMEM_MMA);

    const int GATHER_BLOCKS = (N_NODES * 16 + 127) / 128;   // 8 nodes per 128-thr block
    const int CVT_ITEMS = N_NODES * D / 4;

    cudaMemsetAsync(degi, 0, N_NODES * sizeof(int));

    // #1: degree histogram + x -> fp16
    degx2h_kernel<<<(CVT_ITEMS + 255) / 256, 256>>>(dst, degi, x, f16);
    // #2: exclusive scan
    scan_kernel<<<1, 1024>>>(degi, rowst, cursor);
    // #3: CSR fill
    fill_kernel<<<(N_EDGES + 255) / 256, 256>>>(src, dst, cursor, col);
    // #4: layer-1 gather (ncu capture control)
    gather16_kernel<<<GATHER_BLOCKS, 128>>>(f16, rowst, degi, col, agg16);
    // #5: layer-1 tensor GEMM -> fp16 shadow only
    sage_mma_kernel<<<sms, MMA_THREADS, SMEM_MMA>>>(
        f16, agg16, Ws1, Wn1, b1, (float*)0, f16, 0);
    // #6: layer-2 gather
    gather16_kernel<<<GATHER_BLOCKS, 128>>>(f16, rowst, degi, col, agg16);
    // #7: layer-2 tensor GEMM -> fp32 out with L2 norm
    sage_mma_kernel<<<sms, MMA_THREADS, SMEM_MMA>>>(
        f16, agg16, Ws2, Wn2, b2, out, (__half*)0, 1);
}

// round 17
// speedup vs baseline: 1.0881x; 1.0881x over previous
#include <cuda_runtime.h>
#include <cuda_fp16.h>
#include <cstdint>

#define N_NODES 100000
#define N_EDGES 1600000
#define D 128
#define TILE_R 128
#define SA_K 264                     // padded k-stride (halves)
#define MMA_THREADS 512
#define A_BUF_H (TILE_R * SA_K)      // halves per A buffer
// smem: A0 + A1 + B[128][264]h + bias[128]f + snorm[128][2]f
#define SMEM_MMA (2*A_BUF_H*2 + 128*SA_K*2 + 128*4 + 256*4)   // 204288

// ---------------- device scratch ----------------
__device__ __align__(16) __half g_agg16[(size_t)N_NODES * D];
__device__ __align__(16) __half g_f16[(size_t)N_NODES * D];
__device__ __align__(16) int    g_degi[N_NODES];
__device__ __align__(16) int    g_rowstart[N_NODES];
__device__ __align__(16) int    g_cursor[N_NODES];
__device__ __align__(16) int    g_col[N_EDGES];

// ---------------- helpers ----------------
__device__ __forceinline__ uint32_t smem_u32(const void* p) {
    uint32_t a;
    asm("{ .reg .u64 t; cvta.to.shared.u64 t, %1; cvt.u32.u64 %0, t; }" : "=r"(a) : "l"(p));
    return a;
}
__device__ __forceinline__ void ldsm_x4(uint32_t& r0, uint32_t& r1, uint32_t& r2,
                                        uint32_t& r3, uint32_t addr) {
    asm volatile("ldmatrix.sync.aligned.m8n8.x4.shared.b16 {%0,%1,%2,%3}, [%4];"
                 : "=r"(r0), "=r"(r1), "=r"(r2), "=r"(r3) : "r"(addr));
}
__device__ __forceinline__ void mma16816(float* d, const uint32_t* a,
                                         uint32_t b0, uint32_t b1) {
    asm volatile(
        "mma.sync.aligned.m16n8k16.row.col.f32.f16.f16.f32 "
        "{%0,%1,%2,%3}, {%4,%5,%6,%7}, {%8,%9}, {%0,%1,%2,%3};"
        : "+f"(d[0]), "+f"(d[1]), "+f"(d[2]), "+f"(d[3])
        : "r"(a[0]), "r"(a[1]), "r"(a[2]), "r"(a[3]), "r"(b0), "r"(b1));
}
__device__ __forceinline__ uint32_t h2u(__half2 h) { return *(uint32_t*)&h; }
__device__ __forceinline__ void cp_async16(uint32_t dst, const void* src, int src_sz) {
    asm volatile("cp.async.cg.shared.global [%0], [%1], 16, %2;"
                 :: "r"(dst), "l"(src), "r"(src_sz) : "memory");
}
__device__ __forceinline__ void cp_commit() {
    asm volatile("cp.async.commit_group;" ::: "memory");
}
__device__ __forceinline__ void cp_wait0() {
    asm volatile("cp.async.wait_group 0;" ::: "memory");
}

// ---------------- fused degree histogram + x -> fp16 ----------------
__global__ void degx2h_kernel(const int* __restrict__ dst, int* __restrict__ degi,
                              const float* __restrict__ x, __half* __restrict__ x16) {
    int i = blockIdx.x * blockDim.x + threadIdx.x;
    if (i < N_EDGES) atomicAdd(&degi[dst[i]], 1);
    if (i < N_NODES * D / 4) {
        float4 v = *(const float4*)(x + (size_t)i * 4);
        __half2 a = __floats2half2_rn(v.x, v.y);
        __half2 b = __floats2half2_rn(v.z, v.w);
        *(uint2*)(x16 + (size_t)i * 4) = make_uint2(h2u(a), h2u(b));
    }
}

// ---------------- single-block pass-based exclusive scan ----------------
__global__ void scan_kernel(const int* __restrict__ deg,
                            int* __restrict__ rowstart, int* __restrict__ cursor) {
    __shared__ int wsums[32];
    __shared__ int running_s;
    const int t = threadIdx.x;
    const int lane = t & 31, w = t >> 5;
    if (t == 0) running_s = 0;
    __syncthreads();

    for (int base = 0; base < N_NODES; base += 4096) {
        int i0 = base + t * 4;
        int4 d4 = make_int4(0, 0, 0, 0);
        if (i0 + 3 < N_NODES) d4 = *(const int4*)(deg + i0);
        else {
            if (i0 + 0 < N_NODES) d4.x = deg[i0 + 0];
            if (i0 + 1 < N_NODES) d4.y = deg[i0 + 1];
            if (i0 + 2 < N_NODES) d4.z = deg[i0 + 2];
        }
        int tsum = d4.x + d4.y + d4.z + d4.w;
        int sc = tsum;
#pragma unroll
        for (int m = 1; m < 32; m <<= 1) {
            int u = __shfl_up_sync(0xffffffffu, sc, m);
            if (lane >= m) sc += u;
        }
        if (lane == 31) wsums[w] = sc;
        __syncthreads();
        if (w == 0) {
            int s2 = wsums[lane];
#pragma unroll
            for (int m = 1; m < 32; m <<= 1) {
                int u = __shfl_up_sync(0xffffffffu, s2, m);
                if (lane >= m) s2 += u;
            }
            wsums[lane] = s2;
        }
        __syncthreads();
        int excl = running_s + (w > 0 ? wsums[w - 1] : 0) + sc - tsum;
        int r = excl;
        if (i0 + 0 < N_NODES) { rowstart[i0 + 0] = r; cursor[i0 + 0] = r; } r += d4.x;
        if (i0 + 1 < N_NODES) { rowstart[i0 + 1] = r; cursor[i0 + 1] = r; } r += d4.y;
        if (i0 + 2 < N_NODES) { rowstart[i0 + 2] = r; cursor[i0 + 2] = r; } r += d4.z;
        if (i0 + 3 < N_NODES) { rowstart[i0 + 3] = r; cursor[i0 + 3] = r; }
        int total = wsums[31];
        __syncthreads();
        if (t == 0) running_s += total;
        __syncthreads();
    }
}

__global__ void fill_kernel(const int* __restrict__ src, const int* __restrict__ dst,
                            int* __restrict__ cursor, int* __restrict__ col) {
    int e = blockIdx.x * blockDim.x + threadIdx.x;
    if (e < N_EDGES) {
        int d = dst[e];
        int p = atomicAdd(&cursor[d], 1);
        col[p] = src[e];
    }
}

// ---------------- gather-mean: one node per 16-lane half-warp, uint4 loads ---
// (R15 version — measured 33.8 us, 32 regs, 82.9% occupancy)
__global__ void gather16_kernel(const __half* __restrict__ feat16,
                                const int* __restrict__ row_start,
                                const int* __restrict__ degi,
                                const int* __restrict__ col,
                                __half* __restrict__ agg16) {
    int node = (blockIdx.x * blockDim.x + threadIdx.x) >> 4;
    if (node >= N_NODES) return;
    const int l16 = threadIdx.x & 15;
    const int c8 = l16 << 3;            // 8 halves = 16B per lane
    const int start = row_start[node];
    const int len = degi[node];
    const int end = start + len;

    float acc[8];
#pragma unroll
    for (int i = 0; i < 8; i++) acc[i] = 0.f;

    int e = start;
    for (; e + 4 <= end; e += 4) {
        int s[4];
#pragma unroll
        for (int u = 0; u < 4; u++) s[u] = __ldg(&col[e + u]);
        uint4 v[4];
#pragma unroll
        for (int u = 0; u < 4; u++)
            v[u] = *(const uint4*)(feat16 + (size_t)s[u] * D + c8);
#pragma unroll
        for (int p = 0; p < 2; p++) {
            __half2 q0 = __hadd2(*(__half2*)&v[2*p].x, *(__half2*)&v[2*p+1].x);
            __half2 q1 = __hadd2(*(__half2*)&v[2*p].y, *(__half2*)&v[2*p+1].y);
            __half2 q2 = __hadd2(*(__half2*)&v[2*p].z, *(__half2*)&v[2*p+1].z);
            __half2 q3 = __hadd2(*(__half2*)&v[2*p].w, *(__half2*)&v[2*p+1].w);
            float2 f0 = __half22float2(q0), f1 = __half22float2(q1);
            float2 f2 = __half22float2(q2), f3 = __half22float2(q3);
            acc[0] += f0.x; acc[1] += f0.y; acc[2] += f1.x; acc[3] += f1.y;
            acc[4] += f2.x; acc[5] += f2.y; acc[6] += f3.x; acc[7] += f3.y;
        }
    }
    if (e + 2 <= end) {
        int s0 = __ldg(&col[e]);
        int s1 = __ldg(&col[e + 1]);
        uint4 v0 = *(const uint4*)(feat16 + (size_t)s0 * D + c8);
        uint4 v1 = *(const uint4*)(feat16 + (size_t)s1 * D + c8);
        __half2 q0 = __hadd2(*(__half2*)&v0.x, *(__half2*)&v1.x);
        __half2 q1 = __hadd2(*(__half2*)&v0.y, *(__half2*)&v1.y);
        __half2 q2 = __hadd2(*(__half2*)&v0.z, *(__half2*)&v1.z);
        __half2 q3 = __hadd2(*(__half2*)&v0.w, *(__half2*)&v1.w);
        float2 f0 = __half22float2(q0), f1 = __half22float2(q1);
        float2 f2 = __half22float2(q2), f3 = __half22float2(q3);
        acc[0] += f0.x; acc[1] += f0.y; acc[2] += f1.x; acc[3] += f1.y;
        acc[4] += f2.x; acc[5] += f2.y; acc[6] += f3.x; acc[7] += f3.y;
        e += 2;
    }
    if (e < end) {
        int s = __ldg(&col[e]);
        uint4 v = *(const uint4*)(feat16 + (size_t)s * D + c8);
        float2 f0 = __half22float2(*(__half2*)&v.x);
        float2 f1 = __half22float2(*(__half2*)&v.y);
        float2 f2 = __half22float2(*(__half2*)&v.z);
        float2 f3 = __half22float2(*(__half2*)&v.w);
        acc[0] += f0.x; acc[1] += f0.y; acc[2] += f1.x; acc[3] += f1.y;
        acc[4] += f2.x; acc[5] += f2.y; acc[6] += f3.x; acc[7] += f3.y;
    }
    const float inv = 1.0f / fmaxf((float)len, 1.0f);
    uint4 o;
    o.x = h2u(__floats2half2_rn(acc[0] * inv, acc[1] * inv));
    o.y = h2u(__floats2half2_rn(acc[2] * inv, acc[3] * inv));
    o.z = h2u(__floats2half2_rn(acc[4] * inv, acc[5] * inv));
    o.w = h2u(__floats2half2_rn(acc[6] * inv, acc[7] * inv));
    __stcs((uint4*)(agg16 + (size_t)node * D + c8), o);
}

// ---------------- tensor-core SAGE layer, cp.async double-buffered -----------
// (R13 structure, fully unrolled mainloop — kept from R16, est. -2.8 us/layer)
__global__ void __launch_bounds__(MMA_THREADS, 1)
sage_mma_kernel(const __half* __restrict__ f16feat,
                const __half* __restrict__ agg16,
                const float* __restrict__ Ws,
                const float* __restrict__ Wn,
                const float* __restrict__ bias,
                float* __restrict__ out,       // may be null (layer 1)
                __half* __restrict__ out16,    // may be null (layer 2)
                int do_norm) {
    extern __shared__ __half sh[];
    __half* sA = sh;                               // 2 x [128][SA_K]
    __half* sB = sh + 2 * A_BUF_H;                 // [128][SA_K]
    float* sbias = (float*)(sB + 128 * SA_K);      // [128]
    float* snorm = sbias + 128;                    // [128][2]

    const int tid = threadIdx.x;
    const int wid = tid >> 5;
    const int lane = tid & 31;
    const int warp_m = wid & 7;
    const int warp_n = wid >> 3;

    const uint32_t sA_addr = smem_u32(sA);
    const uint32_t sB_addr = smem_u32(sB);

    // ---- A tile staging via cp.async: 4096 16B chunks, 8 per thread ----
    auto stageA = [&](int tile, int buf) {
        const int row0 = tile * TILE_R;
        const uint32_t bbase = sA_addr + (uint32_t)buf * (A_BUF_H * 2);
#pragma unroll
        for (int i = 0; i < 8; i++) {
            int c = tid + i * MMA_THREADS;       // 0..4095
            int r = c >> 5;
            int cc = c & 31;                     // 16B chunk within row
            int grow = row0 + r;
            int valid = (grow < N_NODES) ? 16 : 0;
            int g = (grow < N_NODES) ? grow : 0;
            const __half* src = (cc < 16)
                ? f16feat + (size_t)g * D + cc * 8
                : agg16 + (size_t)g * D + (cc - 16) * 8;
            cp_async16(bbase + (uint32_t)(r * SA_K * 2 + cc * 16), src, valid);
        }
        cp_commit();
    };

    // ---- stage B (weights) once: row j, quarter q (64 halves) ----
    {
        int j = tid >> 2, q = tid & 3;
        const float* W = (q < 2) ? Ws : Wn;
        const float4* wr = (const float4*)(W + j * D + (q & 1) * 64);
        uint4* drow = (uint4*)(sB + j * SA_K + q * 64);
#pragma unroll
        for (int q2 = 0; q2 < 8; q2++) {
            float4 v0 = wr[q2 * 2], v1 = wr[q2 * 2 + 1];
            drow[q2] = make_uint4(h2u(__floats2half2_rn(v0.x, v0.y)),
                                  h2u(__floats2half2_rn(v0.z, v0.w)),
                                  h2u(__floats2half2_rn(v1.x, v1.y)),
                                  h2u(__floats2half2_rn(v1.z, v1.w)));
        }
    }
    if (tid < 128) sbias[tid] = bias[tid];

    const uint32_t a_off = ((warp_m * 16 + (lane & 15)) * SA_K + (lane >> 4) * 8) * 2;
    const uint32_t b_row = warp_n * 64 + (lane & 15);
    const uint32_t b_base = sB_addr + (b_row * SA_K + (lane >> 4) * 8) * 2;

    const int NT = (N_NODES + TILE_R - 1) / TILE_R;   // 782

    // prologue: prefetch first tile
    if (blockIdx.x < NT) stageA(blockIdx.x, 0);

    int buf = 0;
    for (int tile = blockIdx.x; tile < NT; tile += gridDim.x) {
        const int row0 = tile * TILE_R;

        cp_wait0();
        __syncthreads();

        // prefetch next tile into the other buffer (overlaps with mma below)
        int ntile = tile + gridDim.x;
        if (ntile < NT) stageA(ntile, buf ^ 1);

        // ---- mma mainloop: K = 256 in 16 k16 steps (full unroll) ----
        const uint32_t a_base = sA_addr + (uint32_t)buf * (A_BUF_H * 2) + a_off;
        float acc[8][4];
#pragma unroll
        for (int i = 0; i < 8; i++)
#pragma unroll
            for (int j = 0; j < 4; j++) acc[i][j] = 0.f;

#pragma unroll
        for (int ks = 0; ks < 16; ks++) {
            uint32_t a[4];
            ldsm_x4(a[0], a[1], a[2], a[3], a_base + ks * 32);
#pragma unroll
            for (int nf2 = 0; nf2 < 4; nf2++) {
                uint32_t b0, b1, b2, b3;
                ldsm_x4(b0, b1, b2, b3, b_base + nf2 * 16 * SA_K * 2 + ks * 32);
                mma16816(acc[nf2 * 2 + 0], a, b0, b2);
                mma16816(acc[nf2 * 2 + 1], a, b1, b3);
            }
        }

        // ---- epilogue: bias + (optional) cross-warp L2 norm ----
        const int tg = lane & 3;
        const int rr = lane >> 2;
        const int row_a = warp_m * 16 + rr;
        const int row_b = row_a + 8;

        float ss_a = 0.f, ss_b = 0.f;
#pragma unroll
        for (int nf = 0; nf < 8; nf++) {
            int n0 = warp_n * 64 + nf * 8 + tg * 2;
            acc[nf][0] += sbias[n0]; acc[nf][1] += sbias[n0 + 1];
            acc[nf][2] += sbias[n0]; acc[nf][3] += sbias[n0 + 1];
            ss_a += acc[nf][0] * acc[nf][0] + acc[nf][1] * acc[nf][1];
            ss_b += acc[nf][2] * acc[nf][2] + acc[nf][3] * acc[nf][3];
        }
        ss_a += __shfl_xor_sync(0xffffffffu, ss_a, 1);
        ss_a += __shfl_xor_sync(0xffffffffu, ss_a, 2);
        ss_b += __shfl_xor_sync(0xffffffffu, ss_b, 1);
        ss_b += __shfl_xor_sync(0xffffffffu, ss_b, 2);

        float scale_a = 1.f, scale_b = 1.f;
        if (do_norm) {
            if (tg == 0) {
                snorm[row_a * 2 + warp_n] = ss_a;
                snorm[row_b * 2 + warp_n] = ss_b;
            }
            __syncthreads();
            float fa = snorm[row_a * 2 + 0] + snorm[row_a * 2 + 1];
            float fb = snorm[row_b * 2 + 0] + snorm[row_b * 2 + 1];
            scale_a = 1.0f / fmaxf(sqrtf(fa), 1e-12f);
            scale_b = 1.0f / fmaxf(sqrtf(fb), 1e-12f);
        }

        int grow_a = row0 + row_a;
        int grow_b = row0 + row_b;
#pragma unroll
        for (int nf = 0; nf < 8; nf++) {
            int n0 = warp_n * 64 + nf * 8 + tg * 2;
            if (grow_a < N_NODES) {
                float v0 = acc[nf][0] * scale_a, v1 = acc[nf][1] * scale_a;
                if (out) *(float2*)(out + (size_t)grow_a * D + n0) = make_float2(v0, v1);
                if (out16) *(__half2*)(out16 + (size_t)grow_a * D + n0) = __floats2half2_rn(v0, v1);
            }
            if (grow_b < N_NODES) {
                float v0 = acc[nf][2] * scale_b, v1 = acc[nf][3] * scale_b;
                if (out) *(float2*)(out + (size_t)grow_b * D + n0) = make_float2(v0, v1);
                if (out16) *(__half2*)(out16 + (size_t)grow_b * D + n0) = __floats2half2_rn(v0, v1);
            }
        }
        buf ^= 1;
        __syncthreads();   // all reads of buf done before it is refilled next iter
    }
}

// ---------------- launch ----------------
extern "C" void kernel_launch(void* const* d_in, const int* in_sizes, int n_in,
                              void* d_out, int out_size) {
    const float* x   = (const float*)d_in[0];
    const int* src   = (const int*)d_in[1];
    const int* dst   = (const int*)d_in[2];
    const float* Ws1 = (const float*)d_in[3];
    const float* Wn1 = (const float*)d_in[4];
    const float* b1  = (const float*)d_in[5];
    const float* Ws2 = (const float*)d_in[6];
    const float* Wn2 = (const float*)d_in[7];
    const float* b2  = (const float*)d_in[8];
    float* out = (float*)d_out;

    __half* agg16; cudaGetSymbolAddress((void**)&agg16, g_agg16);
    __half* f16;   cudaGetSymbolAddress((void**)&f16, g_f16);
    int* degi;     cudaGetSymbolAddress((void**)&degi, g_degi);
    int* rowst;    cudaGetSymbolAddress((void**)&rowst, g_rowstart);
    int* cursor;   cudaGetSymbolAddress((void**)&cursor, g_cursor);
    int* col;      cudaGetSymbolAddress((void**)&col, g_col);

    int sms = 148;
    cudaDeviceGetAttribute(&sms, cudaDevAttrMultiProcessorCount, 0);
    cudaFuncSetAttribute(sage_mma_kernel,
                         cudaFuncAttributeMaxDynamicSharedMemorySize, SMEM_MMA);

    const int GATHER_BLOCKS = (N_NODES * 16 + 127) / 128;   // 8 nodes per 128-thr block
    const int CVT_ITEMS = N_NODES * D / 4;

    cudaMemsetAsync(degi, 0, N_NODES * sizeof(int));

    // #1: degree histogram + x -> fp16
    degx2h_kernel<<<(CVT_ITEMS + 255) / 256, 256>>>(dst, degi, x, f16);
    // #2: exclusive scan
    scan_kernel<<<1, 1024>>>(degi, rowst, cursor);
    // #3: CSR fill
    fill_kernel<<<(N_EDGES + 255) / 256, 256>>>(src, dst, cursor, col);
    // #4: layer-1 gather (ncu capture control)
    gather16_kernel<<<GATHER_BLOCKS, 128>>>(f16, rowst, degi, col, agg16);
    // #5: layer-1 tensor GEMM -> fp16 shadow only
    sage_mma_kernel<<<sms, MMA_THREADS, SMEM_MMA>>>(
        f16, agg16, Ws1, Wn1, b1, (float*)0, f16, 0);
    // #6: layer-2 gather
    gather16_kernel<<<GATHER_BLOCKS, 128>>>(f16, rowst, degi, col, agg16);
    // #7: layer-2 tensor GEMM -> fp32 out with L2 norm
    sage_mma_kernel<<<sms, MMA_THREADS, SMEM_MMA>>>(
        f16, agg16, Ws2, Wn2, b2, out, (__half*)0, 1);
}